// round 15
// baseline (speedup 1.0000x reference)
#include <cuda_runtime.h>
#include <cuda_bf16.h>

#define BATCH   2048
#define N0      49
#define CH      768
#define MID     48
#define K1      36
#define K2      24
#define THREADS 256
#define WARPS   8

// Preprocessed weights (device globals).
//   g_w1t[r][j*CH + c] = bf16( se{r}_w1[c, j] )
//   g_w2p[r][((j/4)*CH + c)*4 + (j%4)] = bf16(w2[j,c])
//   g_clswt[o*CH + c]  = cls_w[c, o]  fp32
__device__ __nv_bfloat16 g_w1t[2][MID * CH];
__device__ __nv_bfloat16 g_w2p[2][MID * CH];
__device__ float         g_clswt[5 * CH];

__global__ void convert_weights_kernel(const float* __restrict__ w1a,
                                       const float* __restrict__ w2a,
                                       const float* __restrict__ w1b,
                                       const float* __restrict__ w2b,
                                       const float* __restrict__ clsw) {
    int i = blockIdx.x * blockDim.x + threadIdx.x;
    if (i < MID * CH) {
        int j = i / CH;
        int c = i - j * CH;
        g_w1t[0][i] = __float2bfloat16(w1a[c * MID + j]);
        g_w1t[1][i] = __float2bfloat16(w1b[c * MID + j]);
        int pidx = ((j >> 2) * CH + c) * 4 + (j & 3);
        g_w2p[0][pidx] = __float2bfloat16(w2a[i]);
        g_w2p[1][pidx] = __float2bfloat16(w2b[i]);
    }
    if (i < 5 * CH) {
        int o = i / CH;
        int c = i - o * CH;
        g_clswt[i] = clsw[c * 5 + o];
    }
}

// Shared memory (floats), per CTA for TWO batches:
//   sbufA/B[CH], csumA/B[CH], gatA/B[CH], hbufA/B[MID], tsA/B[64],
//   red[64], listA/B[40] int, unsA/B[16] int, uns2A/B[16] int
#define SM_FLOATS (6*CH + 2*MID + 2*64 + 64 + 2*40 + 2*16 + 2*16)
#define SM_BYTES  (SM_FLOATS * 4)

__global__ __launch_bounds__(THREADS, 4)
void coatgft_kernel(const float* __restrict__ x,
                    const float* __restrict__ b1a, const float* __restrict__ b2a,
                    const float* __restrict__ b1b, const float* __restrict__ b2b,
                    const float* __restrict__ ln_g, const float* __restrict__ ln_b,
                    const float* __restrict__ cls_b,
                    float* __restrict__ out) {
    extern __shared__ float sm[];
    float* sbufA = sm;                   // [CH]
    float* sbufB = sbufA + CH;           // [CH]
    float* csumA = sbufB + CH;           // [CH]
    float* csumB = csumA + CH;           // [CH]
    float* gatA  = csumB + CH;           // [CH]
    float* gatB  = gatA + CH;            // [CH]
    float* hbufA = gatB + CH;            // [MID]
    float* hbufB = hbufA + MID;          // [MID]
    float* tsA   = hbufB + MID;          // [64]
    float* tsB   = tsA + 64;             // [64]
    float* red   = tsB + 64;             // [64]
    int* listA = (int*)(red + 64);       // [40]
    int* listB = listA + 40;             // [40]
    int* unsA  = listB + 40;             // [16]
    int* unsB  = unsA + 16;              // [16]
    int* uns2A = unsB + 16;              // [16]
    int* uns2B = uns2A + 16;             // [16]

    const int tid  = threadIdx.x;
    const int lane = tid & 31;
    const int warp = tid >> 5;
    const int b0   = blockIdx.x * 2;
    const float* __restrict__ xbA = x + (size_t)b0 * N0 * CH;
    const float* __restrict__ xbB = xbA + N0 * CH;

    // ---- colmean + colsum over 49 rows, both batches, float4 (tid<192) ----
    if (tid < 192) {
        float4 aA = make_float4(0.f, 0.f, 0.f, 0.f);
        float4 aB = make_float4(0.f, 0.f, 0.f, 0.f);
        #pragma unroll 7
        for (int r = 0; r < N0; r++) {
            float4 vA = __ldcg((const float4*)(xbA + (size_t)r * CH) + tid);
            float4 vB = __ldcg((const float4*)(xbB + (size_t)r * CH) + tid);
            aA.x += vA.x; aA.y += vA.y; aA.z += vA.z; aA.w += vA.w;
            aB.x += vB.x; aB.y += vB.y; aB.z += vB.z; aB.w += vB.w;
        }
        ((float4*)csumA)[tid] = aA;
        ((float4*)csumB)[tid] = aB;
        ((float4*)sbufA)[tid] = make_float4(aA.x * (1.0f/N0), aA.y * (1.0f/N0),
                                            aA.z * (1.0f/N0), aA.w * (1.0f/N0));
        ((float4*)sbufB)[tid] = make_float4(aB.x * (1.0f/N0), aB.y * (1.0f/N0),
                                            aB.z * (1.0f/N0), aB.w * (1.0f/N0));
    }
    __syncthreads();

    // ================= per-round macro body =================
    #pragma unroll 1
    for (int round = 0; round < 2; round++) {
        const float* b1 = round ? b1b : b1a;
        const float* b2 = round ? b2b : b2a;

        // ---- h = gelu(s @ W1 + b1): 6 outputs per warp, shared weight loads
        {
            const float4* s4A = (const float4*)sbufA;
            const float4* s4B = (const float4*)sbufB;
            const __nv_bfloat16* W1t = g_w1t[round];
            #pragma unroll
            for (int jj = 0; jj < 6; jj++) {
                int j = warp + jj * WARPS;
                const uint2* wr = (const uint2*)(W1t + j * CH);
                float accA = 0.f, accB = 0.f;
                #pragma unroll
                for (int k = 0; k < 6; k++) {
                    int p = lane + 32 * k;
                    uint2 u = wr[p];
                    __nv_bfloat162 h0 = *reinterpret_cast<__nv_bfloat162*>(&u.x);
                    __nv_bfloat162 h1 = *reinterpret_cast<__nv_bfloat162*>(&u.y);
                    float w0 = __low2float(h0), w1v = __high2float(h0);
                    float w2v = __low2float(h1), w3 = __high2float(h1);
                    float4 sA = s4A[p], sB = s4B[p];
                    accA += sA.x * w0 + sA.y * w1v + sA.z * w2v + sA.w * w3;
                    accB += sB.x * w0 + sB.y * w1v + sB.z * w2v + sB.w * w3;
                }
                #pragma unroll
                for (int o = 16; o; o >>= 1) {
                    accA += __shfl_xor_sync(0xffffffffu, accA, o);
                    accB += __shfl_xor_sync(0xffffffffu, accB, o);
                }
                if (lane == 0) {
                    float zA = accA + b1[j];
                    float zB = accB + b1[j];
                    hbufA[j] = 0.5f * zA * (1.0f + erff(zA * 0.70710678118654752f));
                    hbufB[j] = 0.5f * zB * (1.0f + erff(zB * 0.70710678118654752f));
                }
            }
        }
        __syncthreads();

        // ---- gates: 3 channels per thread, shared packed W2 loads ----
        {
            const uint2* W2p = (const uint2*)g_w2p[round];
            #pragma unroll
            for (int cc = 0; cc < 3; cc++) {
                int c = tid + 256 * cc;
                float aA = b2[c], aB = b2[c];
                #pragma unroll
                for (int j4 = 0; j4 < MID / 4; j4++) {
                    uint2 u = W2p[j4 * CH + c];
                    __nv_bfloat162 p0 = *reinterpret_cast<__nv_bfloat162*>(&u.x);
                    __nv_bfloat162 p1 = *reinterpret_cast<__nv_bfloat162*>(&u.y);
                    float w0 = __low2float(p0), w1v = __high2float(p0);
                    float w2v = __low2float(p1), w3 = __high2float(p1);
                    aA += hbufA[4*j4] * w0 + hbufA[4*j4+1] * w1v
                        + hbufA[4*j4+2] * w2v + hbufA[4*j4+3] * w3;
                    aB += hbufB[4*j4] * w0 + hbufB[4*j4+1] * w1v
                        + hbufB[4*j4+2] * w2v + hbufB[4*j4+3] * w3;
                }
                float gA = 1.0f / (1.0f + expf(-aA));
                float gB = 1.0f / (1.0f + expf(-aB));
                if (round == 0) { gatA[c] = gA;  gatB[c] = gB; }
                else            { gatA[c] *= gA; gatB[c] *= gB; }
            }
        }
        __syncthreads();

        // ---- ts: warp per (batch,row) task ----
        {
            const int nrows = round ? K1 : N0;          // 36 or 49
            const int ntasks = 2 * nrows;               // 72 or 98
            for (int t = warp; t < ntasks; t += WARPS) {
                int bb = t >= nrows;
                int i  = bb ? t - nrows : t;
                int r  = round ? (bb ? listB[i] : listA[i]) : i;
                const float4* row = (const float4*)((bb ? xbB : xbA) + (size_t)r * CH);
                const float4* g4p = (const float4*)(bb ? gatB : gatA);
                float acc = 0.f;
                #pragma unroll
                for (int k = 0; k < 6; k++) {
                    float4 a = __ldcg(row + lane + 32 * k);
                    float4 g = g4p[lane + 32 * k];
                    float v;
                    v = a.x * g.x; acc += v * v;
                    v = a.y * g.y; acc += v * v;
                    v = a.z * g.z; acc += v * v;
                    v = a.w * g.w; acc += v * v;
                }
                #pragma unroll
                for (int o = 16; o; o >>= 1) acc += __shfl_xor_sync(0xffffffffu, acc, o);
                if (lane == 0) (bb ? tsB : tsA)[i] = acc;
            }
        }
        __syncthreads();

        // ---- rank-select: tid<nr does A slot tid; tid in [64,64+nr) B ----
        {
            const int nr = round ? K1 : N0;
            const int k  = round ? K2 : K1;
            int slot = -1, bb = 0;
            if (tid < nr) slot = tid;
            else if (tid >= 64 && tid < 64 + nr) { slot = tid - 64; bb = 1; }
            if (slot >= 0) {
                const float* tsP = bb ? tsB : tsA;
                float mine = tsP[slot];
                int rank = 0;
                for (int j = 0; j < nr; j++) {
                    float tj = tsP[j];
                    rank += (tj > mine) || (tj == mine && j < slot);
                }
                if (round == 0) {
                    // slot == row id
                    if (rank < k) (bb ? listB : listA)[rank] = slot;
                    else          (bb ? unsB  : unsA )[rank - k] = slot;
                } else {
                    int row = (bb ? listB : listA)[slot];
                    if (rank >= k) (bb ? uns2B : uns2A)[rank - k] = row;
                }
            }
        }
        __syncthreads();

        // ---- complement colsum + next-s / pooled (tid<192, both batches) ----
        if (tid < 192) {
            float4 cA = ((float4*)csumA)[tid];
            float4 cB = ((float4*)csumB)[tid];
            const int nrem = round ? (K1 - K2) : (N0 - K1);   // 12 or 13
            const int* rA = round ? uns2A : unsA;
            const int* rB = round ? uns2B : unsB;
            for (int i = 0; i < nrem; i++) {
                float4 vA = __ldcg((const float4*)(xbA + (size_t)rA[i] * CH) + tid);
                float4 vB = __ldcg((const float4*)(xbB + (size_t)rB[i] * CH) + tid);
                cA.x -= vA.x; cA.y -= vA.y; cA.z -= vA.z; cA.w -= vA.w;
                cB.x -= vB.x; cB.y -= vB.y; cB.z -= vB.z; cB.w -= vB.w;
            }
            ((float4*)csumA)[tid] = cA;
            ((float4*)csumB)[tid] = cB;
            float inv = round ? (1.0f / K2) : (1.0f / K1);
            float4 gA = ((float4*)gatA)[tid];
            float4 gB = ((float4*)gatB)[tid];
            ((float4*)sbufA)[tid] = make_float4(cA.x * gA.x * inv, cA.y * gA.y * inv,
                                                cA.z * gA.z * inv, cA.w * gA.w * inv);
            ((float4*)sbufB)[tid] = make_float4(cB.x * gB.x * inv, cB.y * gB.y * inv,
                                                cB.z * gB.z * inv, cB.w * gB.w * inv);
        }
        __syncthreads();
    }
    // after round 1: sbufA/B hold pooled vectors

    // ---- LayerNorm stats (both batches) ----
    {
        float vA0 = sbufA[tid], vA1 = sbufA[tid + 256], vA2 = sbufA[tid + 512];
        float vB0 = sbufB[tid], vB1 = sbufB[tid + 256], vB2 = sbufB[tid + 512];
        float p1A = vA0 + vA1 + vA2, p2A = vA0*vA0 + vA1*vA1 + vA2*vA2;
        float p1B = vB0 + vB1 + vB2, p2B = vB0*vB0 + vB1*vB1 + vB2*vB2;
        #pragma unroll
        for (int o = 16; o; o >>= 1) {
            p1A += __shfl_xor_sync(0xffffffffu, p1A, o);
            p2A += __shfl_xor_sync(0xffffffffu, p2A, o);
            p1B += __shfl_xor_sync(0xffffffffu, p1B, o);
            p2B += __shfl_xor_sync(0xffffffffu, p2B, o);
        }
        if (lane == 0) {
            red[warp]      = p1A; red[8 + warp]  = p2A;
            red[16 + warp] = p1B; red[24 + warp] = p2B;
        }
        __syncthreads();
        if (tid < 2) {
            float m = 0.f, m2 = 0.f;
            #pragma unroll
            for (int w = 0; w < 8; w++) {
                m  += red[16 * tid + w];
                m2 += red[16 * tid + 8 + w];
            }
            m  *= (1.0f / CH);
            m2 *= (1.0f / CH);
            red[32 + 2 * tid]     = m;
            red[32 + 2 * tid + 1] = rsqrtf(m2 - m * m + 1e-5f);
        }
        __syncthreads();
        float muA = red[32], invA = red[33];
        float muB = red[34], invB = red[35];
        #pragma unroll
        for (int cc = 0; cc < 3; cc++) {
            int c = tid + 256 * cc;
            float lg = ln_g[c], lb = ln_b[c];
            gatA[c] = (sbufA[c] - muA) * invA * lg + lb;
            gatB[c] = (sbufB[c] - muB) * invB * lg + lb;
        }
    }
    __syncthreads();

    // ---- classifier: 10 outputs (2 batches x 5) over 8 warps ----
    for (int t = warp; t < 10; t += WARPS) {
        int bb = t / 5, o5 = t - 5 * bb;
        const float* src = bb ? gatB : gatA;
        const float* wr = g_clswt + o5 * CH;
        float acc = 0.f;
        #pragma unroll
        for (int k = 0; k < CH / 32; k++)
            acc += src[lane + 32 * k] * wr[lane + 32 * k];
        #pragma unroll
        for (int o = 16; o; o >>= 1) acc += __shfl_xor_sync(0xffffffffu, acc, o);
        if (lane == 0) out[(b0 + bb) * 5 + o5] = acc + cls_b[o5];
    }
}

extern "C" void kernel_launch(void* const* d_in, const int* in_sizes, int n_in,
                              void* d_out, int out_size) {
    const float* x    = (const float*)d_in[0];
    const float* w1a  = (const float*)d_in[1];
    const float* b1a  = (const float*)d_in[2];
    const float* w2a  = (const float*)d_in[3];
    const float* b2a  = (const float*)d_in[4];
    const float* w1b  = (const float*)d_in[5];
    const float* b1b  = (const float*)d_in[6];
    const float* w2b  = (const float*)d_in[7];
    const float* b2b  = (const float*)d_in[8];
    const float* lng  = (const float*)d_in[9];
    const float* lnb  = (const float*)d_in[10];
    const float* clsw = (const float*)d_in[11];
    const float* clsb = (const float*)d_in[12];
    float* out = (float*)d_out;

    cudaFuncSetAttribute(coatgft_kernel,
                         cudaFuncAttributeMaxDynamicSharedMemorySize, SM_BYTES);

    convert_weights_kernel<<<(MID * CH + 255) / 256, 256>>>(w1a, w2a, w1b, w2b, clsw);
    coatgft_kernel<<<BATCH / 2, THREADS, SM_BYTES>>>(x, b1a, b2a, b1b, b2b,
                                                     lng, lnb, clsb, out);
}

// round 16
// speedup vs baseline: 1.8348x; 1.8348x over previous
#include <cuda_runtime.h>
#include <cuda_bf16.h>

#define BATCH   2048
#define N0      49
#define CH      768
#define MID     48
#define K1      36
#define K2      24
#define THREADS 256
#define WARPS   8

// Preprocessed weights (device globals).
//   g_w1t[r][j*CH + c] = bf16( se{r}_w1[c, j] )
//   g_w2p[r][((j/4)*CH + c)*4 + (j%4)] = bf16(w2[j,c])
//   g_clswt[o*CH + c]  = cls_w[c, o]  fp32
__device__ __nv_bfloat16 g_w1t[2][MID * CH];
__device__ __nv_bfloat16 g_w2p[2][MID * CH];
__device__ float         g_clswt[5 * CH];

__global__ void convert_weights_kernel(const float* __restrict__ w1a,
                                       const float* __restrict__ w2a,
                                       const float* __restrict__ w1b,
                                       const float* __restrict__ w2b,
                                       const float* __restrict__ clsw) {
    int i = blockIdx.x * blockDim.x + threadIdx.x;
    if (i < MID * CH) {
        int j = i / CH;
        int c = i - j * CH;
        g_w1t[0][i] = __float2bfloat16(w1a[c * MID + j]);
        g_w1t[1][i] = __float2bfloat16(w1b[c * MID + j]);
        int pidx = ((j >> 2) * CH + c) * 4 + (j & 3);
        g_w2p[0][pidx] = __float2bfloat16(w2a[i]);
        g_w2p[1][pidx] = __float2bfloat16(w2b[i]);
    }
    if (i < 5 * CH) {
        int o = i / CH;
        int c = i - o * CH;
        g_clswt[i] = clsw[c * 5 + o];
    }
}

// Shared memory (floats): sbuf[CH], csum[CH], gat[CH], hbuf[MID],
// ts[64], list[40] int, uns[16] int, uns2[16] int, red[80]
#define SM_FLOATS (CH + CH + CH + MID + 64 + 40 + 16 + 16 + 80)
#define SM_BYTES  (SM_FLOATS * 4)

// W1 GEMV partial: row j of W1t read as uint2 (4 bf16), sbuf as float4
__device__ __forceinline__ float w1_dot(const __nv_bfloat16* __restrict__ w1row,
                                        const float4* __restrict__ s4, int lane) {
    const uint2* wr = (const uint2*)w1row;
    float acc = 0.f;
    #pragma unroll
    for (int k = 0; k < 6; k++) {
        int p = lane + 32 * k;
        uint2 u = wr[p];
        __nv_bfloat162 h0 = *reinterpret_cast<__nv_bfloat162*>(&u.x);
        __nv_bfloat162 h1 = *reinterpret_cast<__nv_bfloat162*>(&u.y);
        float4 s = s4[p];
        acc += s.x * __low2float(h0) + s.y * __high2float(h0)
             + s.z * __low2float(h1) + s.w * __high2float(h1);
    }
    return acc;
}

// gates GEMV for one channel c: packed W2, 12 x LDG.64
__device__ __forceinline__ float w2_dot(const uint2* __restrict__ W2p,
                                        const float* __restrict__ hbuf, int c) {
    float acc = 0.f;
    #pragma unroll
    for (int j4 = 0; j4 < MID / 4; j4++) {
        uint2 u = W2p[j4 * CH + c];
        __nv_bfloat162 p0 = *reinterpret_cast<__nv_bfloat162*>(&u.x);
        __nv_bfloat162 p1 = *reinterpret_cast<__nv_bfloat162*>(&u.y);
        acc += hbuf[4 * j4]     * __low2float(p0)
             + hbuf[4 * j4 + 1] * __high2float(p0)
             + hbuf[4 * j4 + 2] * __low2float(p1)
             + hbuf[4 * j4 + 3] * __high2float(p1);
    }
    return acc;
}

__global__ __launch_bounds__(THREADS, 5)
void coatgft_kernel(const float* __restrict__ x,
                    const float* __restrict__ b1a, const float* __restrict__ b2a,
                    const float* __restrict__ b1b, const float* __restrict__ b2b,
                    const float* __restrict__ ln_g, const float* __restrict__ ln_b,
                    const float* __restrict__ cls_b,
                    float* __restrict__ out) {
    extern __shared__ float sm[];
    float* sbuf = sm;                    // [CH]
    float* csum = sbuf + CH;             // [CH]
    float* gat  = csum + CH;             // [CH]
    float* hbuf = gat + CH;              // [MID]
    float* ts   = hbuf + MID;            // [64]
    int*   list = (int*)(ts + 64);       // [40]
    int*   uns  = list + 40;             // [16]
    int*   uns2 = uns + 16;              // [16]
    float* red  = (float*)(uns2 + 16);   // [80]

    const int tid  = threadIdx.x;
    const int lane = tid & 31;
    const int warp = tid >> 5;
    const int b    = blockIdx.x;
    const float* __restrict__ xb = x + (size_t)b * N0 * CH;

    // ---- colmean + colsum over 49 rows, float4 (threads 0..191) ----
    if (tid < 192) {
        float4 a = make_float4(0.f, 0.f, 0.f, 0.f);
        #pragma unroll 7
        for (int r = 0; r < N0; r++) {
            float4 v = __ldcg((const float4*)(xb + (size_t)r * CH) + tid);
            a.x += v.x; a.y += v.y; a.z += v.z; a.w += v.w;
        }
        ((float4*)csum)[tid] = a;
        float4 m = make_float4(a.x * (1.0f / N0), a.y * (1.0f / N0),
                               a.z * (1.0f / N0), a.w * (1.0f / N0));
        ((float4*)sbuf)[tid] = m;
    }
    __syncthreads();

    // ======================= ROUND 1 (49 -> 36) =============================
    {   // h = gelu(s @ W1 + b1): 6 outputs per warp
        const float4* s4 = (const float4*)sbuf;
        #pragma unroll
        for (int jj = 0; jj < 6; jj++) {
            int j = warp + jj * WARPS;
            float acc = w1_dot(g_w1t[0] + j * CH, s4, lane);
            #pragma unroll
            for (int o = 16; o; o >>= 1) acc += __shfl_xor_sync(0xffffffffu, acc, o);
            if (lane == 0) {
                float z = acc + b1a[j];
                hbuf[j] = 0.5f * z * (1.0f + erff(z * 0.70710678118654752f));
            }
        }
    }
    __syncthreads();

    // gates1: 3 channels per thread (packed W2)
    {
        const uint2* W2p = (const uint2*)g_w2p[0];
        float a0 = b2a[tid]       + w2_dot(W2p, hbuf, tid);
        float a1 = b2a[tid + 256] + w2_dot(W2p, hbuf, tid + 256);
        float a2 = b2a[tid + 512] + w2_dot(W2p, hbuf, tid + 512);
        gat[tid]       = 1.0f / (1.0f + expf(-a0));
        gat[tid + 256] = 1.0f / (1.0f + expf(-a1));
        gat[tid + 512] = 1.0f / (1.0f + expf(-a2));
    }
    __syncthreads();

    // ts1[r] = sum_c (x*g)^2: warp per row, float4
    {
        const float4* g4p = (const float4*)gat;
        #pragma unroll
        for (int ii = 0; ii < 7; ii++) {
            int r = warp + ii * WARPS;
            if (r < N0) {
                const float4* row = (const float4*)(xb + (size_t)r * CH);
                float acc = 0.f;
                #pragma unroll
                for (int k = 0; k < 6; k++) {
                    float4 a = __ldcg(row + lane + 32 * k);
                    float4 g = g4p[lane + 32 * k];
                    float v;
                    v = a.x * g.x; acc += v * v;
                    v = a.y * g.y; acc += v * v;
                    v = a.z * g.z; acc += v * v;
                    v = a.w * g.w; acc += v * v;
                }
                #pragma unroll
                for (int o = 16; o; o >>= 1) acc += __shfl_xor_sync(0xffffffffu, acc, o);
                if (lane == 0) ts[r] = acc;
            }
        }
    }
    __syncthreads();

    // rank-select top-36 (== jax top_k order); 13 unselected to uns
    if (tid < N0) {
        float mine = ts[tid];
        int rank = 0;
        #pragma unroll
        for (int j = 0; j < N0; j++) {
            float tj = ts[j];
            rank += (tj > mine) || (tj == mine && j < tid);
        }
        if (rank < K1) list[rank] = tid;
        else           uns[rank - K1] = tid;
    }
    __syncthreads();

    // ======================= ROUND 2 (36 -> 24) =============================
    // csum36 = csum49 - 13 unselected rows; s2 = gat*csum36/36  (float4)
    if (tid < 192) {
        float4 c = ((float4*)csum)[tid];
        #pragma unroll
        for (int i = 0; i < N0 - K1; i++) {
            float4 v = __ldcg((const float4*)(xb + (size_t)uns[i] * CH) + tid);
            c.x -= v.x; c.y -= v.y; c.z -= v.z; c.w -= v.w;
        }
        ((float4*)csum)[tid] = c;
        float4 g = ((float4*)gat)[tid];
        float4 s = make_float4(c.x * g.x * (1.0f / K1), c.y * g.y * (1.0f / K1),
                               c.z * g.z * (1.0f / K1), c.w * g.w * (1.0f / K1));
        ((float4*)sbuf)[tid] = s;
    }
    __syncthreads();

    {
        const float4* s4 = (const float4*)sbuf;
        #pragma unroll
        for (int jj = 0; jj < 6; jj++) {
            int j = warp + jj * WARPS;
            float acc = w1_dot(g_w1t[1] + j * CH, s4, lane);
            #pragma unroll
            for (int o = 16; o; o >>= 1) acc += __shfl_xor_sync(0xffffffffu, acc, o);
            if (lane == 0) {
                float z = acc + b1b[j];
                hbuf[j] = 0.5f * z * (1.0f + erff(z * 0.70710678118654752f));
            }
        }
    }
    __syncthreads();

    // gat *= gates2
    {
        const uint2* W2p = (const uint2*)g_w2p[1];
        float a0 = b2b[tid]       + w2_dot(W2p, hbuf, tid);
        float a1 = b2b[tid + 256] + w2_dot(W2p, hbuf, tid + 256);
        float a2 = b2b[tid + 512] + w2_dot(W2p, hbuf, tid + 512);
        gat[tid]       *= 1.0f / (1.0f + expf(-a0));
        gat[tid + 256] *= 1.0f / (1.0f + expf(-a1));
        gat[tid + 512] *= 1.0f / (1.0f + expf(-a2));
    }
    __syncthreads();

    // ts2 over 36 selected rows (cumulative gate)
    {
        const float4* g4p = (const float4*)gat;
        #pragma unroll
        for (int ii = 0; ii < 5; ii++) {
            int i = warp + ii * WARPS;
            if (i < K1) {
                const float4* row = (const float4*)(xb + (size_t)list[i] * CH);
                float acc = 0.f;
                #pragma unroll
                for (int k = 0; k < 6; k++) {
                    float4 a = __ldcg(row + lane + 32 * k);
                    float4 g = g4p[lane + 32 * k];
                    float v;
                    v = a.x * g.x; acc += v * v;
                    v = a.y * g.y; acc += v * v;
                    v = a.z * g.z; acc += v * v;
                    v = a.w * g.w; acc += v * v;
                }
                #pragma unroll
                for (int o = 16; o; o >>= 1) acc += __shfl_xor_sync(0xffffffffu, acc, o);
                if (lane == 0) ts[i] = acc;
            }
        }
    }
    __syncthreads();

    // top-24 of 36: record the 12 removed rows
    if (tid < K1) {
        float mine = ts[tid];
        int rank = 0;
        int row = list[tid];
        #pragma unroll
        for (int j = 0; j < K1; j++) {
            float tj = ts[j];
            rank += (tj > mine) || (tj == mine && j < tid);
        }
        if (rank >= K2) uns2[rank - K2] = row;
    }
    __syncthreads();

    // pooled = gat * (csum36 - 12 removed rows) / 24  (float4)
    if (tid < 192) {
        float4 c = ((float4*)csum)[tid];
        #pragma unroll
        for (int i = 0; i < K1 - K2; i++) {
            float4 v = __ldcg((const float4*)(xb + (size_t)uns2[i] * CH) + tid);
            c.x -= v.x; c.y -= v.y; c.z -= v.z; c.w -= v.w;
        }
        float4 g = ((float4*)gat)[tid];
        float4 s = make_float4(c.x * g.x * (1.0f / K2), c.y * g.y * (1.0f / K2),
                               c.z * g.z * (1.0f / K2), c.w * g.w * (1.0f / K2));
        ((float4*)sbuf)[tid] = s;
    }
    __syncthreads();

    // ---- LayerNorm stats ----
    {
        float v0 = sbuf[tid], v1 = sbuf[tid + 256], v2 = sbuf[tid + 512];
        float p1 = v0 + v1 + v2;
        float p2 = v0 * v0 + v1 * v1 + v2 * v2;
        #pragma unroll
        for (int o = 16; o; o >>= 1) {
            p1 += __shfl_xor_sync(0xffffffffu, p1, o);
            p2 += __shfl_xor_sync(0xffffffffu, p2, o);
        }
        if (lane == 0) { red[warp] = p1; red[8 + warp] = p2; }
        __syncthreads();
        if (warp == 0) {
            float m  = (lane < WARPS) ? red[lane]     : 0.f;
            float m2 = (lane < WARPS) ? red[8 + lane] : 0.f;
            #pragma unroll
            for (int o = 4; o; o >>= 1) {
                m  += __shfl_xor_sync(0xffffffffu, m,  o);
                m2 += __shfl_xor_sync(0xffffffffu, m2, o);
            }
            if (lane == 0) {
                m  *= (1.0f / CH);
                m2 *= (1.0f / CH);
                red[16] = m;
                red[17] = rsqrtf(m2 - m * m + 1e-5f);
            }
        }
        __syncthreads();
        float mu = red[16], inv = red[17];
        gat[tid]       = (sbuf[tid]       - mu) * inv * ln_g[tid]       + ln_b[tid];
        gat[tid + 256] = (sbuf[tid + 256] - mu) * inv * ln_g[tid + 256] + ln_b[tid + 256];
        gat[tid + 512] = (sbuf[tid + 512] - mu) * inv * ln_g[tid + 512] + ln_b[tid + 512];
    }
    __syncthreads();

    // ---- classifier: 5 outputs, one warp each ----
    if (warp < 5) {
        const float* wr = g_clswt + warp * CH;
        float acc = 0.f;
        #pragma unroll
        for (int k = 0; k < CH / 32; k++)
            acc += gat[lane + 32 * k] * wr[lane + 32 * k];
        #pragma unroll
        for (int o = 16; o; o >>= 1) acc += __shfl_xor_sync(0xffffffffu, acc, o);
        if (lane == 0) out[b * 5 + warp] = acc + cls_b[warp];
    }
}

extern "C" void kernel_launch(void* const* d_in, const int* in_sizes, int n_in,
                              void* d_out, int out_size) {
    const float* x    = (const float*)d_in[0];
    const float* w1a  = (const float*)d_in[1];
    const float* b1a  = (const float*)d_in[2];
    const float* w2a  = (const float*)d_in[3];
    const float* b2a  = (const float*)d_in[4];
    const float* w1b  = (const float*)d_in[5];
    const float* b1b  = (const float*)d_in[6];
    const float* w2b  = (const float*)d_in[7];
    const float* b2b  = (const float*)d_in[8];
    const float* lng  = (const float*)d_in[9];
    const float* lnb  = (const float*)d_in[10];
    const float* clsw = (const float*)d_in[11];
    const float* clsb = (const float*)d_in[12];
    float* out = (float*)d_out;

    cudaFuncSetAttribute(coatgft_kernel,
                         cudaFuncAttributeMaxDynamicSharedMemorySize, SM_BYTES);

    convert_weights_kernel<<<(MID * CH + 255) / 256, 256>>>(w1a, w2a, w1b, w2b, clsw);
    coatgft_kernel<<<BATCH, THREADS, SM_BYTES>>>(x, b1a, b2a, b1b, b2b,
                                                 lng, lnb, clsb, out);
}